// round 2
// baseline (speedup 1.0000x reference)
#include <cuda_runtime.h>

#define NA   512
#define Fdim 128
#define FEdim 128
#define KX   384          // 2F + FE
#define HID  256
#define Bb   14
#define BB   196          // 14*14
#define NBdim 7168        // 512*14
#define TP   64           // pairs per block
#define KC   32           // K chunk
#define NT   256          // threads per block

// ---------- packed f32x2 helpers ----------
__device__ __forceinline__ unsigned long long pk2(float x, float y) {
    unsigned long long r;
    asm("mov.b64 %0, {%1, %2};" : "=l"(r) : "f"(x), "f"(y));
    return r;
}
__device__ __forceinline__ void upk2(unsigned long long v, float& x, float& y) {
    asm("mov.b64 {%0, %1}, %2;" : "=f"(x), "=f"(y) : "l"(v));
}
__device__ __forceinline__ void fma2(unsigned long long& d, unsigned long long a, unsigned long long b) {
    asm("fma.rn.f32x2 %0, %1, %2, %3;" : "=l"(d) : "l"(a), "l"(b), "l"(d));
}
__device__ __forceinline__ float silu_f(float x) {
    return x / (1.0f + __expf(-x));
}

// ===========================================================================
// Off-diagonal kernel: 64 pairs per block.
//  Phase 1: H = silu(X @ Wo1 + bo1)   X gathered on the fly ([ni|nj|eij])
//  Phase 2: M = H @ Wo2 + bo2
//  Epilogue: M += overlap; write (i,j) block and (j,i)=transpose block,
//            both as contiguous 14-float row runs (via smem staging).
// ===========================================================================
__global__ void __launch_bounds__(NT, 1)
off_kernel(const float* __restrict__ nodes, const float* __restrict__ edges,
           const float* __restrict__ overlap,
           const float* __restrict__ Wo1, const float* __restrict__ bo1,
           const float* __restrict__ Wo2, const float* __restrict__ bo2,
           const int* __restrict__ pi, const int* __restrict__ pj,
           float* __restrict__ out)
{
    extern __shared__ float smem[];
    float* sX = smem;                  // [64][36]   gathered X chunk
    float* sW = sX + TP * 36;          // [32][256]  weight chunk (reused [32][224] in phase 2)
    float* sH = sW + KC * HID;         // [64][256]  hidden activations
    float* sM = sH + TP * HID;         // [64][200]  output blocks staging
    int*   sI = (int*)(sM + TP * 200); // [64]
    int*   sJ = sI + TP;               // [64]

    const int tid = threadIdx.x;
    const int tx = tid & 15;           // col group
    const int ty = tid >> 4;           // row group
    const int pbase = blockIdx.x * TP;

    if (tid < TP) {
        sI[tid] = pi[pbase + tid];
        sJ[tid] = pj[pbase + tid];
    }
    __syncthreads();

    const int n0 = tx << 4;            // 16 HID cols per thread

    // -------------------- Phase 1: GEMM1 --------------------
    unsigned long long acc[4][8];
    #pragma unroll
    for (int s = 0; s < 4; s++)
        #pragma unroll
        for (int v = 0; v < 8; v++) acc[s][v] = 0ull;

    // gather mapping: thread loads 8 consecutive k of one pair-row
    const int gp = tid >> 2;
    const int gk = (tid & 3) << 3;
    const int gi = sI[gp];
    const int gj = sJ[gp];
    const float* srcA = nodes + gi * Fdim;
    const float* srcB = nodes + gj * Fdim;
    const float* srcC = edges + (gi * NA + gj) * FEdim;

    for (int kk = 0; kk < KX; kk += KC) {
        // gather X chunk [64][32]  (each 32-chunk lies fully in one region)
        const float* src = (kk < Fdim)     ? (srcA + kk + gk)
                         : (kk < 2 * Fdim) ? (srcB + (kk - Fdim) + gk)
                                           : (srcC + (kk - 2 * Fdim) + gk);
        float4 v0 = *(const float4*)(src);
        float4 v1 = *(const float4*)(src + 4);
        *(float4*)(sX + gp * 36 + gk)     = v0;
        *(float4*)(sX + gp * 36 + gk + 4) = v1;

        // load Wo1 chunk [32][256] (contiguous region)
        {
            const float4* wsrc = (const float4*)(Wo1 + kk * HID);
            float4* wdst = (float4*)sW;
            #pragma unroll
            for (int t = 0; t < 8; t++) wdst[tid + t * NT] = wsrc[tid + t * NT];
        }
        __syncthreads();

        #pragma unroll
        for (int k = 0; k < KC; k++) {
            const ulonglong2* bp = (const ulonglong2*)(sW + k * HID + n0);
            ulonglong2 b0 = bp[0], b1 = bp[1], b2 = bp[2], b3 = bp[3];
            #pragma unroll
            for (int s = 0; s < 4; s++) {
                float a = sX[(ty + (s << 4)) * 36 + k];
                unsigned long long aa = pk2(a, a);
                fma2(acc[s][0], aa, b0.x); fma2(acc[s][1], aa, b0.y);
                fma2(acc[s][2], aa, b1.x); fma2(acc[s][3], aa, b1.y);
                fma2(acc[s][4], aa, b2.x); fma2(acc[s][5], aa, b2.y);
                fma2(acc[s][6], aa, b3.x); fma2(acc[s][7], aa, b3.y);
            }
        }
        __syncthreads();
    }

    // bias + silu -> sH
    #pragma unroll
    for (int v = 0; v < 8; v++) {
        float blo = bo1[n0 + 2 * v];
        float bhi = bo1[n0 + 2 * v + 1];
        #pragma unroll
        for (int s = 0; s < 4; s++) {
            float lo, hi;
            upk2(acc[s][v], lo, hi);
            lo = silu_f(lo + blo);
            hi = silu_f(hi + bhi);
            const int row = ty + (s << 4);
            sH[row * HID + n0 + 2 * v]     = lo;
            sH[row * HID + n0 + 2 * v + 1] = hi;
        }
    }
    __syncthreads();

    // -------------------- Phase 2: GEMM2 --------------------
    unsigned long long a2[4][7];
    #pragma unroll
    for (int s = 0; s < 4; s++)
        #pragma unroll
        for (int v = 0; v < 7; v++) a2[s][v] = 0ull;

    const int c0 = tx * 14;  // 14 output cols per thread (tx<14 valid)

    for (int kk = 0; kk < HID; kk += KC) {
        // load Wo2 chunk [32][196] into [32][224] padded-with-zero layout
        #pragma unroll
        for (int t = 0; t < 28; t++) {
            int e = tid + t * NT;            // e < 7168 exactly
            int row = e / 224;
            int col = e - row * 224;
            sW[row * 224 + col] = (col < BB) ? Wo2[(kk + row) * BB + col] : 0.0f;
        }
        __syncthreads();

        #pragma unroll
        for (int k = 0; k < KC; k++) {
            const unsigned long long* bp = (const unsigned long long*)(sW + k * 224 + c0);
            unsigned long long b[7];
            #pragma unroll
            for (int v = 0; v < 7; v++) b[v] = bp[v];
            #pragma unroll
            for (int s = 0; s < 4; s++) {
                float a = sH[(ty + (s << 4)) * HID + kk + k];
                unsigned long long aa = pk2(a, a);
                #pragma unroll
                for (int v = 0; v < 7; v++) fma2(a2[s][v], aa, b[v]);
            }
        }
        __syncthreads();
    }

    // bias -> sM (only tx<14 hold valid columns)
    if (tx < 14) {
        #pragma unroll
        for (int v = 0; v < 7; v++) {
            float blo = bo2[c0 + 2 * v];
            float bhi = bo2[c0 + 2 * v + 1];
            #pragma unroll
            for (int s = 0; s < 4; s++) {
                float lo, hi;
                upk2(a2[s][v], lo, hi);
                const int p = ty + (s << 4);
                sM[p * 200 + c0 + 2 * v]     = lo + blo;
                sM[p * 200 + c0 + 2 * v + 1] = hi + bhi;
            }
        }
    }
    __syncthreads();

    // add overlap_pair (coalesced read)
    {
        const float* ovb = overlap + pbase * BB;
        for (int e = tid; e < TP * BB; e += NT) {
            int p = e / BB;
            sM[p * 200 + (e - p * BB)] += ovb[e];
        }
    }
    __syncthreads();

    // write (i,j) blocks: contiguous 14-float runs per (pair,row)
    for (int e = tid; e < TP * BB; e += NT) {
        int p = e / BB;
        int idx = e - p * BB;
        int r = idx / Bb;
        int c = idx - r * Bb;
        out[(sI[p] * Bb + r) * NBdim + sJ[p] * Bb + c] = sM[p * 200 + idx];
    }
    // write (j,i) transposed blocks: iterate so addresses stay contiguous
    for (int e = tid; e < TP * BB; e += NT) {
        int p = e / BB;
        int t = e - p * BB;
        int c = t / Bb;
        int r = t - c * Bb;
        out[(sJ[p] * Bb + c) * NBdim + sI[p] * Bb + r] = sM[p * 200 + r * Bb + c];
    }
}

// ===========================================================================
// Diagonal kernel: one block per atom.
// x = [node_i | edge_ii];  m = silu(x@W1+b1)@W2+b2;  out block = atom_block + m
// ===========================================================================
__global__ void __launch_bounds__(256)
diag_kernel(const float* __restrict__ nodes, const float* __restrict__ edges,
            const float* __restrict__ ablk,
            const float* __restrict__ W1, const float* __restrict__ b1,
            const float* __restrict__ W2, const float* __restrict__ b2,
            float* __restrict__ out)
{
    __shared__ float sx[HID];
    __shared__ float sh[HID];
    const int i = blockIdx.x;
    const int tid = threadIdx.x;

    sx[tid] = (tid < Fdim) ? nodes[i * Fdim + tid]
                           : edges[(i * NA + i) * FEdim + (tid - Fdim)];
    __syncthreads();

    float acc = b1[tid];
    #pragma unroll 8
    for (int k = 0; k < HID; k++)
        acc = fmaf(sx[k], W1[k * HID + tid], acc);
    sh[tid] = silu_f(acc);
    __syncthreads();

    if (tid < BB) {
        float a2 = b2[tid];
        #pragma unroll 8
        for (int k = 0; k < HID; k++)
            a2 = fmaf(sh[k], W2[k * BB + tid], a2);
        int r = tid / Bb;
        int c = tid - r * Bb;
        out[(i * Bb + r) * NBdim + i * Bb + c] = a2 + ablk[i * BB + tid];
    }
}

// ===========================================================================
extern "C" void kernel_launch(void* const* d_in, const int* in_sizes, int n_in,
                              void* d_out, int out_size)
{
    const float* nodes = (const float*)d_in[0];
    const float* edges = (const float*)d_in[1];
    const float* ablk  = (const float*)d_in[2];
    const float* ovlp  = (const float*)d_in[3];
    const float* W1    = (const float*)d_in[4];
    const float* b1    = (const float*)d_in[5];
    const float* W2    = (const float*)d_in[6];
    const float* b2    = (const float*)d_in[7];
    const float* Wo1   = (const float*)d_in[8];
    const float* bo1   = (const float*)d_in[9];
    const float* Wo2   = (const float*)d_in[10];
    const float* bo2   = (const float*)d_in[11];
    const int*   pi    = (const int*)d_in[12];
    const int*   pj    = (const int*)d_in[13];
    float* out = (float*)d_out;

    const int P = in_sizes[12];  // 130816, divisible by TP=64
    const int smem_bytes = (TP * 36 + KC * HID + TP * HID + TP * 200) * 4 + TP * 2 * 4;

    cudaFuncSetAttribute(off_kernel, cudaFuncAttributeMaxDynamicSharedMemorySize, smem_bytes);

    diag_kernel<<<NA, 256>>>(nodes, edges, ablk, W1, b1, W2, b2, out);
    off_kernel<<<P / TP, NT, smem_bytes>>>(nodes, edges, ovlp, Wo1, bo1, Wo2, bo2, pi, pj, out);
}

// round 6
// speedup vs baseline: 4.2370x; 4.2370x over previous
#include <cuda_runtime.h>
#include <cuda_bf16.h>

#define NA    512
#define Fdim  128
#define FEdim 128
#define HID   256
#define Bb    14
#define BB    196
#define NBdim 7168
#define TP    128          // pairs per CTA (tc path)
#define NT    256
#define N2PAD 224          // padded GEMM2 N (196 -> 224)

// Fallback (FFMA) tiling
#define FTP   64           // pairs per block
#define KC    32           // K chunk
#define KX    384

// -------- arch-feature detection: tcgen05 only exists on the 'a' target ----
#if defined(__CUDA_ARCH__) && \
    (defined(__CUDA_ARCH_FEAT_SM103_ALL) || \
     (defined(__CUDA_ARCH_SPECIFIC__) && (__CUDA_ARCH_SPECIFIC__ == 1030)) || \
     (defined(__CUDA_ARCH_FAMILY_SPECIFIC__) && (__CUDA_ARCH_FAMILY_SPECIFIC__ == 1030)))
#define HAS_TC 1
#else
#define HAS_TC 0
#endif

// ---------------- device scratch ----------------
__device__ __align__(16) __nv_bfloat16 g_W1T[HID * 384];     // [256][384]
__device__ __align__(16) __nv_bfloat16 g_W2T[N2PAD * HID];   // [224][256]
__device__ int g_tc_ok = 0;   // set by real tc kernel; fallback skips if set

// ---------------- smem byte offsets (tc kernel) ----------------
#define SM_X0    0         // X chunk buf0  [128][64]bf16 = 16384
#define SM_X1    16384
#define SM_W0    32768     // W1 chunk buf0 [256][64]bf16 = 32768
#define SM_W1    65536
#define SM_H     0         // H [128][256]bf16, 4 chunk-blocks of 16384
#define SM_W2_0  65536     // W2 chunk [224][64]bf16 = 28672
#define SM_W2_1  94208
#define SM_M     0         // sM [128][201] f32 = 102912
#define SM_BARS  122880    // +0 tmem ptr, +8 bar0, +16 bar1
#define SM_B1    123904    // bo1 256 f32
#define SM_B2    124928    // bo2 padded 224 f32
#define SM_IJ    125952    // 128 i + 128 j int
#define SMEM_TOTAL 126976

#define SW(o) ((o) ^ (((o) >> 3) & 0x70))

// idesc: dtype=F32, a=BF16, b=BF16, K-major, M=128
#define IDESC1 ((1u<<4)|(1u<<7)|(1u<<10)|((HID/8)<<17)|((128/16)<<24))    // N=256
#define IDESC2 ((1u<<4)|(1u<<7)|(1u<<10)|((N2PAD/8)<<17)|((128/16)<<24))  // N=224

// ---------------- generic helpers ----------------
__device__ __forceinline__ float silu_f(float x) { return x / (1.0f + __expf(-x)); }
__device__ __forceinline__ unsigned f2bf2(float lo, float hi) {
    __nv_bfloat162 h = __floats2bfloat162_rn(lo, hi);
    return *(unsigned*)&h;
}
__device__ __forceinline__ unsigned smem_u32(const void* p) {
    unsigned a;
    asm("{ .reg .u64 t; cvta.to.shared.u64 t, %1; cvt.u32.u64 %0, t; }" : "=r"(a) : "l"(p));
    return a;
}
// packed f32x2 helpers (fallback path)
__device__ __forceinline__ unsigned long long pk2(float x, float y) {
    unsigned long long r;
    asm("mov.b64 %0, {%1, %2};" : "=l"(r) : "f"(x), "f"(y));
    return r;
}
__device__ __forceinline__ void upk2(unsigned long long v, float& x, float& y) {
    asm("mov.b64 {%0, %1}, %2;" : "=f"(x), "=f"(y) : "l"(v));
}
__device__ __forceinline__ void fma2(unsigned long long& d, unsigned long long a, unsigned long long b) {
    asm("fma.rn.f32x2 %0, %1, %2, %3;" : "=l"(d) : "l"(a), "l"(b), "l"(d));
}

#if HAS_TC
// ---------------- tcgen05 PTX helpers (only compiled on the 'a' target) ----
__device__ __forceinline__ unsigned long long mk_desc(unsigned addr) {
    const unsigned long long base =
        (2ull << 61) | (1ull << 46) | (64ull << 32) | (1ull << 16);   // SW128, LBO=1, SBO=64
    return base | ((unsigned long long)(addr >> 4) & 0x3FFF);
}
__device__ __forceinline__ void mma_f16_ss(unsigned d, unsigned long long a,
                                           unsigned long long b, unsigned idesc, bool acc) {
    unsigned e = acc ? 1u : 0u;
    asm volatile(
        "{\n\t.reg .pred p;\n\t"
        "setp.ne.u32 p, %5, 0;\n\t"
        "tcgen05.mma.cta_group::1.kind::f16 [%0], %1, %2, %3, {%4,%4,%4,%4}, p;\n\t}"
        :: "r"(d), "l"(a), "l"(b), "r"(idesc), "r"(0u), "r"(e) : "memory");
}
__device__ __forceinline__ void tmem_alloc(unsigned smem_addr, unsigned ncols) {
    asm volatile("tcgen05.alloc.cta_group::1.sync.aligned.shared::cta.b32 [%0], %1;"
                 :: "r"(smem_addr), "r"(ncols) : "memory");
}
__device__ __forceinline__ void tmem_dealloc(unsigned tmem, unsigned ncols) {
    asm volatile("tcgen05.dealloc.cta_group::1.sync.aligned.b32 %0, %1;" :: "r"(tmem), "r"(ncols));
}
__device__ __forceinline__ void tmem_relinquish() {
    asm volatile("tcgen05.relinquish_alloc_permit.cta_group::1.sync.aligned;");
}
__device__ __forceinline__ void mbar_init(unsigned addr, unsigned cnt) {
    asm volatile("mbarrier.init.shared.b64 [%0], %1;" :: "r"(addr), "r"(cnt) : "memory");
}
__device__ __forceinline__ void mbar_wait(unsigned addr, unsigned parity) {
    asm volatile(
        "{\n\t.reg .pred P1;\n\t"
        "W%=:\n\t"
        "mbarrier.try_wait.parity.acquire.cta.shared::cta.b64 P1, [%0], %1, 0x989680;\n\t"
        "@P1 bra.uni D%=;\n\t"
        "bra.uni W%=;\n\t"
        "D%=:\n\t}"
        :: "r"(addr), "r"(parity) : "memory");
}
__device__ __forceinline__ void mma_commit(unsigned bar) {
    asm volatile("tcgen05.commit.cta_group::1.mbarrier::arrive::one.shared::cluster.b64 [%0];"
                 :: "r"(bar) : "memory");
}
__device__ __forceinline__ void fence_async_smem() {
    asm volatile("fence.proxy.async.shared::cta;" ::: "memory");
}
__device__ __forceinline__ void tc_fence_after() {
    asm volatile("tcgen05.fence::after_thread_sync;" ::: "memory");
}
__device__ __forceinline__ void tc_fence_before() {
    asm volatile("tcgen05.fence::before_thread_sync;" ::: "memory");
}
__device__ __forceinline__ void wait_ld() {
    asm volatile("tcgen05.wait::ld.sync.aligned;" ::: "memory");
}
__device__ __forceinline__ void ldtm32(unsigned* r, unsigned addr) {
    asm volatile(
        "tcgen05.ld.sync.aligned.32x32b.x32.b32 "
        "{%0,%1,%2,%3,%4,%5,%6,%7,%8,%9,%10,%11,%12,%13,%14,%15,"
        "%16,%17,%18,%19,%20,%21,%22,%23,%24,%25,%26,%27,%28,%29,%30,%31}, [%32];"
        : "=r"(r[0]),"=r"(r[1]),"=r"(r[2]),"=r"(r[3]),"=r"(r[4]),"=r"(r[5]),"=r"(r[6]),"=r"(r[7]),
          "=r"(r[8]),"=r"(r[9]),"=r"(r[10]),"=r"(r[11]),"=r"(r[12]),"=r"(r[13]),"=r"(r[14]),"=r"(r[15]),
          "=r"(r[16]),"=r"(r[17]),"=r"(r[18]),"=r"(r[19]),"=r"(r[20]),"=r"(r[21]),"=r"(r[22]),"=r"(r[23]),
          "=r"(r[24]),"=r"(r[25]),"=r"(r[26]),"=r"(r[27]),"=r"(r[28]),"=r"(r[29]),"=r"(r[30]),"=r"(r[31])
        : "r"(addr));
}
__device__ __forceinline__ void ldtm4(unsigned& a, unsigned& b, unsigned& c, unsigned& d, unsigned addr) {
    asm volatile("tcgen05.ld.sync.aligned.32x32b.x4.b32 {%0,%1,%2,%3}, [%4];"
                 : "=r"(a), "=r"(b), "=r"(c), "=r"(d) : "r"(addr));
}
#endif  // HAS_TC

// ===========================================================================
// prep: transpose + bf16-convert weights into device scratch
// ===========================================================================
__global__ void prep_kernel(const float* __restrict__ Wo1, const float* __restrict__ Wo2) {
    int stride = gridDim.x * blockDim.x;
    int t = blockIdx.x * blockDim.x + threadIdx.x;
    for (int e = t; e < HID * 384; e += stride) {
        int n = e / 384, k = e - n * 384;
        g_W1T[e] = __float2bfloat16(Wo1[k * HID + n]);
    }
    for (int e = t; e < N2PAD * HID; e += stride) {
        int n = e / HID, k = e - n * HID;
        g_W2T[e] = (n < BB) ? __float2bfloat16(Wo2[k * BB + n]) : __float2bfloat16(0.0f);
    }
}

// ===========================================================================
// Off-diagonal tcgen05 kernel: 128 pairs per CTA (stub on non-'a' targets)
// ===========================================================================
__global__ void __launch_bounds__(NT, 1)
off_tc_kernel(const float* __restrict__ nodes, const float* __restrict__ edges,
              const float* __restrict__ overlap,
              const float* __restrict__ bo1, const float* __restrict__ bo2,
              const int* __restrict__ pi, const int* __restrict__ pj,
              float* __restrict__ out)
{
#if HAS_TC
    extern __shared__ char smem[];
    const unsigned sb = smem_u32(smem);
    const int tid = threadIdx.x;
    const int pbase = blockIdx.x * TP;

    if (blockIdx.x == 0 && tid == 0) g_tc_ok = 1;

    int*   sI  = (int*)(smem + SM_IJ);
    int*   sJ  = sI + TP;
    float* sB1 = (float*)(smem + SM_B1);
    float* sB2 = (float*)(smem + SM_B2);

    if (tid < TP) { sI[tid] = pi[pbase + tid]; sJ[tid] = pj[pbase + tid]; }
    sB1[tid] = bo1[tid];
    if (tid < N2PAD) sB2[tid] = (tid < BB) ? bo2[tid] : 0.0f;

    if (tid == 0) {
        mbar_init(sb + SM_BARS + 8, 1);
        mbar_init(sb + SM_BARS + 16, 1);
    }
    if (tid < 32) {
        tmem_alloc(sb + SM_BARS, 512);
        tmem_relinquish();
    }
    __syncthreads();

    unsigned tmem;
    asm volatile("ld.shared.b32 %0, [%1];" : "=r"(tmem) : "r"(sb + SM_BARS));
    const unsigned bar0 = sb + SM_BARS + 8;
    const unsigned bar1 = sb + SM_BARS + 16;
    int cnt0 = 0, cnt1 = 0;

    // gather mapping: 2 threads per pair-row, 32 floats each per chunk
    const int xrow = tid >> 1;
    const int xhalf = tid & 1;
    const int xi = sI[xrow], xj = sJ[xrow];

    // ---------------- GEMM1: D1[128,256] = X[128,384] @ Wo1, K chunks of 64
    #pragma unroll 1
    for (int c = 0; c < 6; c++) {
        const int b = c & 1;
        if (c >= 2) {
            if (b == 0) { mbar_wait(bar0, cnt0 & 1); cnt0++; }
            else        { mbar_wait(bar1, cnt1 & 1); cnt1++; }
        }
        // X chunk gather+convert -> swizzled smem [128][64]bf16
        {
            const float* s;
            if (c < 2)      s = nodes + (size_t)xi * Fdim + c * 64;
            else if (c < 4) s = nodes + (size_t)xj * Fdim + (c - 2) * 64;
            else            s = edges + ((size_t)xi * NA + xj) * FEdim + (c - 4) * 64;
            s += xhalf * 32;
            char* xdst = smem + (b ? SM_X1 : SM_X0);
            #pragma unroll
            for (int g = 0; g < 4; g++) {
                float4 v0 = *(const float4*)(s + g * 8);
                float4 v1 = *(const float4*)(s + g * 8 + 4);
                uint4 w;
                w.x = f2bf2(v0.x, v0.y); w.y = f2bf2(v0.z, v0.w);
                w.z = f2bf2(v1.x, v1.y); w.w = f2bf2(v1.z, v1.w);
                unsigned off = xrow * 128 + xhalf * 64 + g * 16;
                *(uint4*)(xdst + SW(off)) = w;
            }
        }
        // W1 chunk [256][64]bf16 -> swizzled smem (one row per thread)
        {
            const uint4* wsrc = (const uint4*)(g_W1T + (size_t)tid * 384 + c * 64);
            char* wdst = smem + (b ? SM_W1 : SM_W0);
            #pragma unroll
            for (int g = 0; g < 8; g++) {
                uint4 v = wsrc[g];
                *(uint4*)(wdst + SW(tid * 128 + g * 16)) = v;
            }
        }
        fence_async_smem();
        __syncthreads();
        if (tid == 0) {
            unsigned long long ad = mk_desc(sb + (b ? SM_X1 : SM_X0));
            unsigned long long bd = mk_desc(sb + (b ? SM_W1 : SM_W0));
            #pragma unroll
            for (int ks = 0; ks < 4; ks++)
                mma_f16_ss(tmem, ad + ks * 2, bd + ks * 2, IDESC1, (c > 0) || (ks > 0));
            mma_commit(b ? bar1 : bar0);
        }
    }
    // all GEMM1 MMAs done (both buffers)
    mbar_wait(bar0, cnt0 & 1); cnt0++;
    mbar_wait(bar1, cnt1 & 1); cnt1++;
    tc_fence_after();

    // ---------------- epilogue1: D1 -> silu -> bf16 H in smem; prefill W2 chunks 0,1
    if (tid < 128) {
        const int row = tid;
        unsigned regs[32];
        #pragma unroll 1
        for (int cb = 0; cb < 8; cb++) {
            ldtm32(regs, tmem + cb * 32);
            wait_ld();
            #pragma unroll
            for (int t = 0; t < 8; t++) {
                int n0 = cb * 32 + t * 4;
                float a0 = silu_f(__uint_as_float(regs[t * 4 + 0]) + sB1[n0 + 0]);
                float a1 = silu_f(__uint_as_float(regs[t * 4 + 1]) + sB1[n0 + 1]);
                float a2 = silu_f(__uint_as_float(regs[t * 4 + 2]) + sB1[n0 + 2]);
                float a3 = silu_f(__uint_as_float(regs[t * 4 + 3]) + sB1[n0 + 3]);
                uint2 w; w.x = f2bf2(a0, a1); w.y = f2bf2(a2, a3);
                unsigned off = row * 128 + ((n0 & 63) << 1);
                *(uint2*)(smem + SM_H + ((n0 >> 6) << 14) + SW(off)) = w;
            }
        }
        tc_fence_before();
    } else {
        int t0 = tid - 128;
        for (int e = t0; e < 2 * N2PAD; e += 128) {
            int q = e / N2PAD, n = e - q * N2PAD;
            const uint4* src = (const uint4*)(g_W2T + (size_t)n * HID + q * 64);
            char* dst = smem + (q ? SM_W2_1 : SM_W2_0);
            #pragma unroll
            for (int g = 0; g < 8; g++) {
                uint4 v = src[g];
                *(uint4*)(dst + SW(n * 128 + g * 16)) = v;
            }
        }
    }
    fence_async_smem();
    __syncthreads();

    // ---------------- GEMM2: D2[128,224] = H[128,256] @ Wo2pad, K chunks of 64
    #pragma unroll 1
    for (int q = 0; q < 4; q++) {
        const int b = q & 1;
        if (q >= 2) {
            if (b == 0) { mbar_wait(bar0, cnt0 & 1); cnt0++; }
            else        { mbar_wait(bar1, cnt1 & 1); cnt1++; }
            if (tid < N2PAD) {
                const uint4* src = (const uint4*)(g_W2T + (size_t)tid * HID + q * 64);
                char* dst = smem + (b ? SM_W2_1 : SM_W2_0);
                #pragma unroll
                for (int g = 0; g < 8; g++) {
                    uint4 v = src[g];
                    *(uint4*)(dst + SW(tid * 128 + g * 16)) = v;
                }
            }
            fence_async_smem();
            __syncthreads();
        }
        if (tid == 0) {
            unsigned long long ad = mk_desc(sb + SM_H + q * 16384);
            unsigned long long bd = mk_desc(sb + (b ? SM_W2_1 : SM_W2_0));
            #pragma unroll
            for (int ks = 0; ks < 4; ks++)
                mma_f16_ss(tmem + 256, ad + ks * 2, bd + ks * 2, IDESC2, (q > 0) || (ks > 0));
            mma_commit(b ? bar1 : bar0);
        }
    }
    mbar_wait(bar0, cnt0 & 1); cnt0++;
    mbar_wait(bar1, cnt1 & 1); cnt1++;
    tc_fence_after();

    // ---------------- epilogue2: D2 + bias -> sM [128][201] f32
    if (tid < 128) {
        const int row = tid;
        float* rowM = (float*)(smem + SM_M) + row * 201;
        unsigned regs[32];
        #pragma unroll 1
        for (int cb = 0; cb < 6; cb++) {
            ldtm32(regs, tmem + 256 + cb * 32);
            wait_ld();
            #pragma unroll
            for (int c = 0; c < 32; c++)
                rowM[cb * 32 + c] = __uint_as_float(regs[c]) + sB2[cb * 32 + c];
        }
        unsigned r0, r1, r2, r3;
        ldtm4(r0, r1, r2, r3, tmem + 256 + 192);
        wait_ld();
        rowM[192] = __uint_as_float(r0) + sB2[192];
        rowM[193] = __uint_as_float(r1) + sB2[193];
        rowM[194] = __uint_as_float(r2) + sB2[194];
        rowM[195] = __uint_as_float(r3) + sB2[195];
        tc_fence_before();
    }
    __syncthreads();

    // add overlap (coalesced)
    {
        const float* ovb = overlap + (size_t)pbase * BB;
        float* sM = (float*)(smem + SM_M);
        for (int e = tid; e < TP * BB; e += NT) {
            int p = e / BB;
            sM[p * 201 + (e - p * BB)] += ovb[e];
        }
    }
    __syncthreads();

    // write (i,j) blocks + (j,i) transposed blocks (contiguous 14-float runs)
    {
        const float* sM = (const float*)(smem + SM_M);
        for (int e = tid; e < TP * BB; e += NT) {
            int p = e / BB;
            int idx = e - p * BB;
            int r = idx / Bb;
            int c = idx - r * Bb;
            out[(size_t)(sI[p] * Bb + r) * NBdim + sJ[p] * Bb + c] = sM[p * 201 + idx];
        }
        for (int e = tid; e < TP * BB; e += NT) {
            int p = e / BB;
            int t = e - p * BB;
            int c = t / Bb;
            int r = t - c * Bb;
            out[(size_t)(sJ[p] * Bb + c) * NBdim + sI[p] * Bb + r] = sM[p * 201 + r * Bb + c];
        }
    }
    __syncthreads();
    if (tid < 32) tmem_dealloc(tmem, 512);
#endif  // HAS_TC  (stub variant: does nothing; g_tc_ok stays 0 -> fallback runs)
}

// ===========================================================================
// FFMA fallback off-diagonal kernel (R1, known-passing). Skips if tc ran.
// ===========================================================================
__global__ void __launch_bounds__(NT, 1)
off_kernel(const float* __restrict__ nodes, const float* __restrict__ edges,
           const float* __restrict__ overlap,
           const float* __restrict__ Wo1, const float* __restrict__ bo1,
           const float* __restrict__ Wo2, const float* __restrict__ bo2,
           const int* __restrict__ pi, const int* __restrict__ pj,
           float* __restrict__ out)
{
    if (g_tc_ok) return;

    extern __shared__ float fsm[];
    float* sX = fsm;                   // [64][36]
    float* sW = sX + FTP * 36;         // [32][256]
    float* sH = sW + KC * HID;         // [64][256]
    float* sM = sH + FTP * HID;        // [64][200]
    int*   sI = (int*)(sM + FTP * 200);
    int*   sJ = sI + FTP;

    const int tid = threadIdx.x;
    const int tx = tid & 15;
    const int ty = tid >> 4;
    const int pbase = blockIdx.x * FTP;

    if (tid < FTP) {
        sI[tid] = pi[pbase + tid];
        sJ[tid] = pj[pbase + tid];
    }
    __syncthreads();

    const int n0 = tx << 4;

    unsigned long long acc[4][8];
    #pragma unroll
    for (int s = 0; s < 4; s++)
        #pragma unroll
        for (int v = 0; v < 8; v++) acc[s][v] = 0ull;

    const int gp = tid >> 2;
    const int gk = (tid & 3) << 3;
    const int gi = sI[gp];
    const int gj = sJ[gp];
    const float* srcA = nodes + gi * Fdim;
    const float* srcB = nodes + gj * Fdim;
    const float* srcC = edges + ((size_t)gi * NA + gj) * FEdim;

    for (int kk = 0; kk < KX; kk += KC) {
        const float* src = (kk < Fdim)     ? (srcA + kk + gk)
                         : (kk < 2 * Fdim) ? (srcB + (kk - Fdim) + gk)
                                           : (srcC + (kk - 2 * Fdim) + gk);
        float4 v0 = *(const float4*)(src);
        float4 v1 = *(const float4*)(src + 4);
        *(float4*)(sX + gp * 36 + gk)     = v0;
        *(float4*)(sX + gp * 36 + gk + 4) = v1;

        {
            const float4* wsrc = (const float4*)(Wo1 + kk * HID);
            float4* wdst = (float4*)sW;
            #pragma unroll
            for (int t = 0; t < 8; t++) wdst[tid + t * NT] = wsrc[tid + t * NT];
        }
        __syncthreads();

        #pragma unroll
        for (int k = 0; k < KC; k++) {
            const ulonglong2* bp = (const ulonglong2*)(sW + k * HID + n0);
            ulonglong2 b0 = bp[0], b1 = bp[1], b2 = bp[2], b3 = bp[3];
            #pragma unroll
            for (int s = 0; s < 4; s++) {
                float a = sX[(ty + (s << 4)) * 36 + k];
                unsigned long long aa = pk2(a, a);
                fma2(acc[s][0], aa, b0.x); fma2(acc[s][1], aa, b0.y);
                fma2(acc[s][2], aa, b1.x); fma2(acc[s][3], aa, b1.y);
                fma2(acc[s][4], aa, b2.x); fma2(acc[s][5], aa, b2.y);
                fma2(acc[s][6], aa, b3.x); fma2(acc[s][7], aa, b3.y);
            }
        }
        __syncthreads();
    }

    #pragma unroll
    for (int v = 0; v < 8; v++) {
        float blo = bo1[n0 + 2 * v];
        float bhi = bo1[n0 + 2 * v + 1];
        #pragma unroll
        for (int s = 0; s < 4; s++) {
            float lo, hi;
            upk2(acc[s][v], lo, hi);
            lo = silu_f(lo + blo);
            hi = silu_f(hi + bhi);
            const int row = ty + (s << 4);
            sH[row * HID + n0 + 2 * v]     = lo;
            sH[row * HID + n0 + 2 * v + 1] = hi;
        }
    }
    __syncthreads();

    unsigned long long a2[4][7];
    #pragma unroll
    for (int s = 0; s < 4; s++)
        #pragma unroll
        for (int v = 0; v < 7; v++) a2[s][v] = 0ull;

    const int c0 = tx * 14;

    for (int kk = 0; kk < HID; kk += KC) {
        #pragma unroll
        for (int t = 0; t < 28; t++) {
            int e = tid + t * NT;
            int row = e / N2PAD;
            int col = e - row * N2PAD;
            sW[row * N2PAD + col] = (col < BB) ? Wo2[(kk + row) * BB + col] : 0.0f;
        }
        __syncthreads();

        #pragma unroll
        for (int k = 0; k < KC; k++) {
            const unsigned long long* bp = (const unsigned long long*)(sW + k * N2PAD + c0);
            unsigned long long b[7];
            #pragma unroll
            for (int v = 0; v < 7; v++) b[v] = bp[v];
            #pragma unroll
            for (int s = 0; s < 4; s++) {
                float a = sH[(ty + (s << 4)) * HID + kk + k];
                unsigned long long aa = pk2(a, a);
                #pragma unroll
                for (int v = 0; v < 7; v++) fma2(a2[s][v], aa, b[v]);
            }
        }
        __syncthreads();
    }

    if (tx < 14) {
        #pragma unroll
        for (int v = 0; v < 7; v++) {
            float blo = bo2[c0 + 2 * v];
            float bhi = bo2[c0 + 2 * v + 1];
            #pragma unroll
            for (int s = 0; s < 4; s++) {
                float lo, hi;
                upk2(a2[s][v], lo, hi);
                const int p = ty + (s << 4);
                sM[p * 200 + c0 + 2 * v]     = lo + blo;
                sM[p * 200 + c0 + 2 * v + 1] = hi + bhi;
            }
        }
    }
    __syncthreads();

    {
        const float* ovb = overlap + (size_t)pbase * BB;
        for (int e = tid; e < FTP * BB; e += NT) {
            int p = e / BB;
            sM[p * 200 + (e - p * BB)] += ovb[e];
        }
    }
    __syncthreads();

    for (int e = tid; e < FTP * BB; e += NT) {
        int p = e / BB;
        int idx = e - p * BB;
        int r = idx / Bb;
        int c = idx - r * Bb;
        out[(size_t)(sI[p] * Bb + r) * NBdim + sJ[p] * Bb + c] = sM[p * 200 + idx];
    }
    for (int e = tid; e < FTP * BB; e += NT) {
        int p = e / BB;
        int t = e - p * BB;
        int c = t / Bb;
        int r = t - c * Bb;
        out[(size_t)(sJ[p] * Bb + c) * NBdim + sI[p] * Bb + r] = sM[p * 200 + r * Bb + c];
    }
}

// ===========================================================================
// Diagonal kernel (tiny, FFMA everywhere)
// ===========================================================================
__global__ void __launch_bounds__(256)
diag_kernel(const float* __restrict__ nodes, const float* __restrict__ edges,
            const float* __restrict__ ablk,
            const float* __restrict__ W1, const float* __restrict__ b1,
            const float* __restrict__ W2, const float* __restrict__ b2,
            float* __restrict__ out)
{
    __shared__ float sx[HID];
    __shared__ float sh[HID];
    const int i = blockIdx.x;
    const int tid = threadIdx.x;

    sx[tid] = (tid < Fdim) ? nodes[i * Fdim + tid]
                           : edges[((size_t)i * NA + i) * FEdim + (tid - Fdim)];
    __syncthreads();

    float acc = b1[tid];
    #pragma unroll 8
    for (int k = 0; k < HID; k++)
        acc = fmaf(sx[k], W1[k * HID + tid], acc);
    sh[tid] = silu_f(acc);
    __syncthreads();

    if (tid < BB) {
        float a2 = b2[tid];
        #pragma unroll 8
        for (int k = 0; k < HID; k++)
            a2 = fmaf(sh[k], W2[k * BB + tid], a2);
        int r = tid / Bb;
        int c = tid - r * Bb;
        out[(size_t)(i * Bb + r) * NBdim + i * Bb + c] = a2 + ablk[i * BB + tid];
    }
}

// ===========================================================================
extern "C" void kernel_launch(void* const* d_in, const int* in_sizes, int n_in,
                              void* d_out, int out_size)
{
    const float* nodes = (const float*)d_in[0];
    const float* edges = (const float*)d_in[1];
    const float* ablk  = (const float*)d_in[2];
    const float* ovlp  = (const float*)d_in[3];
    const float* W1    = (const float*)d_in[4];
    const float* b1    = (const float*)d_in[5];
    const float* W2    = (const float*)d_in[6];
    const float* b2    = (const float*)d_in[7];
    const float* Wo1   = (const float*)d_in[8];
    const float* bo1   = (const float*)d_in[9];
    const float* Wo2   = (const float*)d_in[10];
    const float* bo2   = (const float*)d_in[11];
    const int*   pi    = (const int*)d_in[12];
    const int*   pj    = (const int*)d_in[13];
    float* out = (float*)d_out;

    const int P = in_sizes[12];   // 130816 = 1022*128 = 2044*64

    const int fb_smem = (FTP * 36 + KC * HID + FTP * HID + FTP * 200) * 4 + FTP * 2 * 4;
    cudaFuncSetAttribute(off_tc_kernel, cudaFuncAttributeMaxDynamicSharedMemorySize, SMEM_TOTAL);
    cudaFuncSetAttribute(off_kernel, cudaFuncAttributeMaxDynamicSharedMemorySize, fb_smem);

    prep_kernel<<<148, 256>>>(Wo1, Wo2);
    diag_kernel<<<NA, 256>>>(nodes, edges, ablk, W1, b1, W2, b2, out);
    // tcgen05 path (real on sm_103a cubin; no-op stub on compute_103 fallback)
    off_tc_kernel<<<P / TP, NT, SMEM_TOTAL>>>(nodes, edges, ovlp, bo1, bo2, pi, pj, out);
    // FFMA fallback: early-exits if the tc kernel did the work
    off_kernel<<<P / FTP, NT, fb_smem>>>(nodes, edges, ovlp, Wo1, bo1, Wo2, bo2, pi, pj, out);
}

// round 7
// speedup vs baseline: 6.3711x; 1.5037x over previous
#include <cuda_runtime.h>
#include <cuda_bf16.h>

#define NA    512
#define Fdim  128
#define FEdim 128
#define HID   256
#define Bb    14
#define BB    196
#define NBdim 7168
#define TP    128          // pairs per CTA (tc path)
#define NT    256
#define N2PAD 224          // padded GEMM2 N (196 -> 224)

// Fallback (FFMA) tiling
#define FTP   64           // pairs per block
#define KC    32           // K chunk
#define KX    384

// -------- arch-feature detection: tcgen05 only exists on the 'a' target ----
#if defined(__CUDA_ARCH__) && \
    (defined(__CUDA_ARCH_FEAT_SM103_ALL) || \
     (defined(__CUDA_ARCH_SPECIFIC__) && (__CUDA_ARCH_SPECIFIC__ == 1030)) || \
     (defined(__CUDA_ARCH_FAMILY_SPECIFIC__) && (__CUDA_ARCH_FAMILY_SPECIFIC__ == 1030)))
#define HAS_TC 1
#else
#define HAS_TC 0
#endif

// ---------------- device scratch ----------------
__device__ __align__(16) __nv_bfloat16 g_W1T[HID * 384];     // [256][384]
__device__ __align__(16) __nv_bfloat16 g_W2T[N2PAD * HID];   // [224][256]
__device__ int g_tc_ok = 0;   // set by real tc kernel; fallback skips if set

// ---------------- smem byte offsets (tc kernel, ~104KB for 2 CTAs/SM) ------
#define SM_X0    0         // X chunk buf0  [128][64]bf16 = 16384
#define SM_X1    16384
#define SM_W0    32768     // W1 chunk buf0 [256][64]bf16 = 32768
#define SM_W1    65536     // W1 chunk buf1                (phase1 top: 98304)
#define SM_H     0         // H [128][256]bf16, 4 chunk-blocks of 16384 (0..65536)
#define SM_W2    65536     // W2 chunk [224][64]bf16 = 28672 (..94208), single buf
#define SM_M     0         // sM [128][201] f32 = 102912
#define SM_BARS  102912    // +0 tmem ptr, +8 bar0, +16 bar1
#define SM_B1    102944    // bo1 256 f32
#define SM_B2    103968    // bo2 padded 224 f32
#define SM_IJ    104864    // 128 i + 128 j int
#define SMEM_TOTAL 105984

#define SW(o) ((o) ^ (((o) >> 3) & 0x70))

// idesc: dtype=F32, a=BF16, b=BF16, K-major, M=128
#define IDESC1 ((1u<<4)|(1u<<7)|(1u<<10)|((HID/8)<<17)|((128/16)<<24))    // N=256
#define IDESC2 ((1u<<4)|(1u<<7)|(1u<<10)|((N2PAD/8)<<17)|((128/16)<<24))  // N=224

// ---------------- generic helpers ----------------
__device__ __forceinline__ float silu_f(float x) { return x / (1.0f + __expf(-x)); }
__device__ __forceinline__ unsigned f2bf2(float lo, float hi) {
    __nv_bfloat162 h = __floats2bfloat162_rn(lo, hi);
    return *(unsigned*)&h;
}
__device__ __forceinline__ unsigned smem_u32(const void* p) {
    unsigned a;
    asm("{ .reg .u64 t; cvta.to.shared.u64 t, %1; cvt.u32.u64 %0, t; }" : "=r"(a) : "l"(p));
    return a;
}
// packed f32x2 helpers (fallback path)
__device__ __forceinline__ unsigned long long pk2(float x, float y) {
    unsigned long long r;
    asm("mov.b64 %0, {%1, %2};" : "=l"(r) : "f"(x), "f"(y));
    return r;
}
__device__ __forceinline__ void upk2(unsigned long long v, float& x, float& y) {
    asm("mov.b64 {%0, %1}, %2;" : "=f"(x), "=f"(y) : "l"(v));
}
__device__ __forceinline__ void fma2(unsigned long long& d, unsigned long long a, unsigned long long b) {
    asm("fma.rn.f32x2 %0, %1, %2, %3;" : "=l"(d) : "l"(a), "l"(b), "l"(d));
}

#if HAS_TC
// ---------------- tcgen05 PTX helpers (only compiled on the 'a' target) ----
__device__ __forceinline__ unsigned long long mk_desc(unsigned addr) {
    const unsigned long long base =
        (2ull << 61) | (1ull << 46) | (64ull << 32) | (1ull << 16);   // SW128, LBO=1, SBO=64
    return base | ((unsigned long long)(addr >> 4) & 0x3FFF);
}
__device__ __forceinline__ void mma_f16_ss(unsigned d, unsigned long long a,
                                           unsigned long long b, unsigned idesc, bool acc) {
    unsigned e = acc ? 1u : 0u;
    asm volatile(
        "{\n\t.reg .pred p;\n\t"
        "setp.ne.u32 p, %5, 0;\n\t"
        "tcgen05.mma.cta_group::1.kind::f16 [%0], %1, %2, %3, {%4,%4,%4,%4}, p;\n\t}"
        :: "r"(d), "l"(a), "l"(b), "r"(idesc), "r"(0u), "r"(e) : "memory");
}
__device__ __forceinline__ void tmem_alloc(unsigned smem_addr, unsigned ncols) {
    asm volatile("tcgen05.alloc.cta_group::1.sync.aligned.shared::cta.b32 [%0], %1;"
                 :: "r"(smem_addr), "r"(ncols) : "memory");
}
__device__ __forceinline__ void tmem_dealloc(unsigned tmem, unsigned ncols) {
    asm volatile("tcgen05.dealloc.cta_group::1.sync.aligned.b32 %0, %1;" :: "r"(tmem), "r"(ncols));
}
__device__ __forceinline__ void tmem_relinquish() {
    asm volatile("tcgen05.relinquish_alloc_permit.cta_group::1.sync.aligned;");
}
__device__ __forceinline__ void mbar_init(unsigned addr, unsigned cnt) {
    asm volatile("mbarrier.init.shared.b64 [%0], %1;" :: "r"(addr), "r"(cnt) : "memory");
}
__device__ __forceinline__ void mbar_wait(unsigned addr, unsigned parity) {
    asm volatile(
        "{\n\t.reg .pred P1;\n\t"
        "W%=:\n\t"
        "mbarrier.try_wait.parity.acquire.cta.shared::cta.b64 P1, [%0], %1, 0x989680;\n\t"
        "@P1 bra.uni D%=;\n\t"
        "bra.uni W%=;\n\t"
        "D%=:\n\t}"
        :: "r"(addr), "r"(parity) : "memory");
}
__device__ __forceinline__ void mma_commit(unsigned bar) {
    asm volatile("tcgen05.commit.cta_group::1.mbarrier::arrive::one.shared::cluster.b64 [%0];"
                 :: "r"(bar) : "memory");
}
__device__ __forceinline__ void fence_async_smem() {
    asm volatile("fence.proxy.async.shared::cta;" ::: "memory");
}
__device__ __forceinline__ void tc_fence_after() {
    asm volatile("tcgen05.fence::after_thread_sync;" ::: "memory");
}
__device__ __forceinline__ void tc_fence_before() {
    asm volatile("tcgen05.fence::before_thread_sync;" ::: "memory");
}
__device__ __forceinline__ void wait_ld() {
    asm volatile("tcgen05.wait::ld.sync.aligned;" ::: "memory");
}
__device__ __forceinline__ void ldtm32(unsigned* r, unsigned addr) {
    asm volatile(
        "tcgen05.ld.sync.aligned.32x32b.x32.b32 "
        "{%0,%1,%2,%3,%4,%5,%6,%7,%8,%9,%10,%11,%12,%13,%14,%15,"
        "%16,%17,%18,%19,%20,%21,%22,%23,%24,%25,%26,%27,%28,%29,%30,%31}, [%32];"
        : "=r"(r[0]),"=r"(r[1]),"=r"(r[2]),"=r"(r[3]),"=r"(r[4]),"=r"(r[5]),"=r"(r[6]),"=r"(r[7]),
          "=r"(r[8]),"=r"(r[9]),"=r"(r[10]),"=r"(r[11]),"=r"(r[12]),"=r"(r[13]),"=r"(r[14]),"=r"(r[15]),
          "=r"(r[16]),"=r"(r[17]),"=r"(r[18]),"=r"(r[19]),"=r"(r[20]),"=r"(r[21]),"=r"(r[22]),"=r"(r[23]),
          "=r"(r[24]),"=r"(r[25]),"=r"(r[26]),"=r"(r[27]),"=r"(r[28]),"=r"(r[29]),"=r"(r[30]),"=r"(r[31])
        : "r"(addr));
}
__device__ __forceinline__ void ldtm4(unsigned& a, unsigned& b, unsigned& c, unsigned& d, unsigned addr) {
    asm volatile("tcgen05.ld.sync.aligned.32x32b.x4.b32 {%0,%1,%2,%3}, [%4];"
                 : "=r"(a), "=r"(b), "=r"(c), "=r"(d) : "r"(addr));
}
#endif  // HAS_TC

// ===========================================================================
// prep: transpose + bf16-convert weights into device scratch
// ===========================================================================
__global__ void prep_kernel(const float* __restrict__ Wo1, const float* __restrict__ Wo2) {
    int stride = gridDim.x * blockDim.x;
    int t = blockIdx.x * blockDim.x + threadIdx.x;
    for (int e = t; e < HID * 384; e += stride) {
        int n = e / 384, k = e - n * 384;
        g_W1T[e] = __float2bfloat16(Wo1[k * HID + n]);
    }
    for (int e = t; e < N2PAD * HID; e += stride) {
        int n = e / HID, k = e - n * HID;
        g_W2T[e] = (n < BB) ? __float2bfloat16(Wo2[k * BB + n]) : __float2bfloat16(0.0f);
    }
}

// ===========================================================================
// Off-diagonal tcgen05 kernel: 128 pairs per CTA, 2 CTAs per SM
// ===========================================================================
__global__ void __launch_bounds__(NT, 2)
off_tc_kernel(const float* __restrict__ nodes, const float* __restrict__ edges,
              const float* __restrict__ overlap,
              const float* __restrict__ bo1, const float* __restrict__ bo2,
              const int* __restrict__ pi, const int* __restrict__ pj,
              float* __restrict__ out)
{
#if HAS_TC
    extern __shared__ char smem[];
    const unsigned sb = smem_u32(smem);
    const int tid = threadIdx.x;
    const int pbase = blockIdx.x * TP;

    if (blockIdx.x == 0 && tid == 0) g_tc_ok = 1;

    int*   sI  = (int*)(smem + SM_IJ);
    int*   sJ  = sI + TP;
    float* sB1 = (float*)(smem + SM_B1);
    float* sB2 = (float*)(smem + SM_B2);

    if (tid < TP) { sI[tid] = pi[pbase + tid]; sJ[tid] = pj[pbase + tid]; }
    sB1[tid] = bo1[tid];
    if (tid < N2PAD) sB2[tid] = (tid < BB) ? bo2[tid] : 0.0f;

    if (tid == 0) {
        mbar_init(sb + SM_BARS + 8, 1);
        mbar_init(sb + SM_BARS + 16, 1);
    }
    if (tid < 32) {
        tmem_alloc(sb + SM_BARS, 256);   // D1 0..255; D2 reuses 0..223
        tmem_relinquish();
    }
    __syncthreads();

    unsigned tmem;
    asm volatile("ld.shared.b32 %0, [%1];" : "=r"(tmem) : "r"(sb + SM_BARS));
    const unsigned bar0 = sb + SM_BARS + 8;
    const unsigned bar1 = sb + SM_BARS + 16;
    int cnt0 = 0, cnt1 = 0;

    // gather mapping: 8 lanes per pair-row segment (coalesced 32B/lane)
    const int gseg = tid & 7;          // 8-float segment within 64-float chunk
    const int grow0 = tid >> 3;        // base row; rows grow0 + it*32

    // ---------------- GEMM1: D1[128,256] = X[128,384] @ Wo1, K chunks of 64
    #pragma unroll 1
    for (int c = 0; c < 6; c++) {
        const int b = c & 1;
        if (c >= 2) {
            if (b == 0) { mbar_wait(bar0, cnt0 & 1); cnt0++; }
            else        { mbar_wait(bar1, cnt1 & 1); cnt1++; }
        }
        // X chunk gather+convert -> swizzled smem [128][64]bf16 (coalesced)
        {
            char* xdst = smem + (b ? SM_X1 : SM_X0);
            #pragma unroll
            for (int it = 0; it < 4; it++) {
                const int p = grow0 + it * 32;
                const int xi = sI[p], xj = sJ[p];
                const float* s;
                if (c < 2)      s = nodes + (size_t)xi * Fdim + c * 64;
                else if (c < 4) s = nodes + (size_t)xj * Fdim + (c - 2) * 64;
                else            s = edges + ((size_t)xi * NA + xj) * FEdim + (c - 4) * 64;
                s += gseg * 8;
                float4 v0 = *(const float4*)(s);
                float4 v1 = *(const float4*)(s + 4);
                uint4 w;
                w.x = f2bf2(v0.x, v0.y); w.y = f2bf2(v0.z, v0.w);
                w.z = f2bf2(v1.x, v1.y); w.w = f2bf2(v1.z, v1.w);
                *(uint4*)(xdst + SW(p * 128 + gseg * 16)) = w;
            }
        }
        // W1 chunk [256][64]bf16 -> swizzled smem (index-linear, coalesced)
        {
            char* wdst = smem + (b ? SM_W1 : SM_W0);
            #pragma unroll
            for (int t = 0; t < 8; t++) {
                int e = tid + t * NT;         // 0..2047
                int row = e >> 3, g = e & 7;
                uint4 v = *(const uint4*)(g_W1T + (size_t)row * 384 + c * 64 + g * 8);
                *(uint4*)(wdst + SW(row * 128 + g * 16)) = v;
            }
        }
        fence_async_smem();
        __syncthreads();
        if (tid == 0) {
            unsigned long long ad = mk_desc(sb + (b ? SM_X1 : SM_X0));
            unsigned long long bd = mk_desc(sb + (b ? SM_W1 : SM_W0));
            #pragma unroll
            for (int ks = 0; ks < 4; ks++)
                mma_f16_ss(tmem, ad + ks * 2, bd + ks * 2, IDESC1, (c > 0) || (ks > 0));
            mma_commit(b ? bar1 : bar0);
        }
    }
    // all GEMM1 MMAs done (both buffers)
    mbar_wait(bar0, cnt0 & 1); cnt0++;
    mbar_wait(bar1, cnt1 & 1); cnt1++;
    tc_fence_after();

    // ---------------- epilogue1: D1 -> silu -> bf16 H in smem; prefill W2 chunk 0
    if (tid < 128) {
        const int row = tid;
        unsigned regs[32];
        #pragma unroll 1
        for (int cb = 0; cb < 8; cb++) {
            ldtm32(regs, tmem + cb * 32);
            wait_ld();
            #pragma unroll
            for (int t = 0; t < 8; t++) {
                int n0 = cb * 32 + t * 4;
                float a0 = silu_f(__uint_as_float(regs[t * 4 + 0]) + sB1[n0 + 0]);
                float a1 = silu_f(__uint_as_float(regs[t * 4 + 1]) + sB1[n0 + 1]);
                float a2 = silu_f(__uint_as_float(regs[t * 4 + 2]) + sB1[n0 + 2]);
                float a3 = silu_f(__uint_as_float(regs[t * 4 + 3]) + sB1[n0 + 3]);
                uint2 w; w.x = f2bf2(a0, a1); w.y = f2bf2(a2, a3);
                unsigned off = row * 128 + ((n0 & 63) << 1);
                *(uint2*)(smem + SM_H + ((n0 >> 6) << 14) + SW(off)) = w;
            }
        }
        tc_fence_before();
    } else {
        // W2 chunk 0 (single buffer) — index-linear, coalesced
        int t0 = tid - 128;
        for (int e = t0; e < N2PAD * 8; e += 128) {
            int row = e >> 3, g = e & 7;
            uint4 v = *(const uint4*)(g_W2T + (size_t)row * HID + g * 8);
            *(uint4*)(smem + SM_W2 + SW(row * 128 + g * 16)) = v;
        }
    }
    fence_async_smem();
    __syncthreads();

    // ---------------- GEMM2: D2[128,224] = H[128,256] @ Wo2pad (D2 reuses D1 cols)
    #pragma unroll 1
    for (int q = 0; q < 4; q++) {
        if (q > 0) {
            mbar_wait(bar0, cnt0 & 1); cnt0++;    // prev MMA done reading W2 buf
            #pragma unroll
            for (int t = 0; t < 7; t++) {
                int e = tid + t * NT;             // 0..1791
                if (e < N2PAD * 8) {
                    int row = e >> 3, g = e & 7;
                    uint4 v = *(const uint4*)(g_W2T + (size_t)row * HID + q * 64 + g * 8);
                    *(uint4*)(smem + SM_W2 + SW(row * 128 + g * 16)) = v;
                }
            }
            fence_async_smem();
            __syncthreads();
        }
        if (tid == 0) {
            tc_fence_after();   // order epilogue1 LDTMs before D overwrite (q=0)
            unsigned long long ad = mk_desc(sb + SM_H + q * 16384);
            unsigned long long bd = mk_desc(sb + SM_W2);
            #pragma unroll
            for (int ks = 0; ks < 4; ks++)
                mma_f16_ss(tmem, ad + ks * 2, bd + ks * 2, IDESC2, (q > 0) || (ks > 0));
            mma_commit(bar0);
        }
    }
    mbar_wait(bar0, cnt0 & 1); cnt0++;
    tc_fence_after();

    // ---------------- epilogue2: D2 + bias -> sM [128][201] f32
    if (tid < 128) {
        const int row = tid;
        float* rowM = (float*)(smem + SM_M) + row * 201;
        unsigned regs[32];
        #pragma unroll 1
        for (int cb = 0; cb < 6; cb++) {
            ldtm32(regs, tmem + cb * 32);
            wait_ld();
            #pragma unroll
            for (int c = 0; c < 32; c++)
                rowM[cb * 32 + c] = __uint_as_float(regs[c]) + sB2[cb * 32 + c];
        }
        unsigned r0, r1, r2, r3;
        ldtm4(r0, r1, r2, r3, tmem + 192);
        wait_ld();
        rowM[192] = __uint_as_float(r0) + sB2[192];
        rowM[193] = __uint_as_float(r1) + sB2[193];
        rowM[194] = __uint_as_float(r2) + sB2[194];
        rowM[195] = __uint_as_float(r3) + sB2[195];
        tc_fence_before();
    }
    __syncthreads();

    // add overlap (coalesced)
    {
        const float* ovb = overlap + (size_t)pbase * BB;
        float* sM = (float*)(smem + SM_M);
        for (int e = tid; e < TP * BB; e += NT) {
            int p = e / BB;
            sM[p * 201 + (e - p * BB)] += ovb[e];
        }
    }
    __syncthreads();

    // write (i,j) blocks + (j,i) transposed blocks (contiguous 14-float runs)
    {
        const float* sM = (const float*)(smem + SM_M);
        for (int e = tid; e < TP * BB; e += NT) {
            int p = e / BB;
            int idx = e - p * BB;
            int r = idx / Bb;
            int c = idx - r * Bb;
            out[(size_t)(sI[p] * Bb + r) * NBdim + sJ[p] * Bb + c] = sM[p * 201 + idx];
        }
        for (int e = tid; e < TP * BB; e += NT) {
            int p = e / BB;
            int t = e - p * BB;
            int c = t / Bb;
            int r = t - c * Bb;
            out[(size_t)(sJ[p] * Bb + c) * NBdim + sI[p] * Bb + r] = sM[p * 201 + r * Bb + c];
        }
    }
    __syncthreads();
    if (tid < 32) tmem_dealloc(tmem, 256);
#endif  // HAS_TC  (stub variant: does nothing; g_tc_ok stays 0 -> fallback runs)
}

// ===========================================================================
// FFMA fallback off-diagonal kernel (known-passing). Skips if tc ran.
// ===========================================================================
__global__ void __launch_bounds__(NT, 1)
off_kernel(const float* __restrict__ nodes, const float* __restrict__ edges,
           const float* __restrict__ overlap,
           const float* __restrict__ Wo1, const float* __restrict__ bo1,
           const float* __restrict__ Wo2, const float* __restrict__ bo2,
           const int* __restrict__ pi, const int* __restrict__ pj,
           float* __restrict__ out)
{
    if (g_tc_ok) return;

    extern __shared__ float fsm[];
    float* sX = fsm;                   // [64][36]
    float* sW = sX + FTP * 36;         // [32][256]
    float* sH = sW + KC * HID;         // [64][256]
    float* sM = sH + FTP * HID;        // [64][200]
    int*   sI = (int*)(sM + FTP * 200);
    int*   sJ = sI + FTP;

    const int tid = threadIdx.x;
    const int tx = tid & 15;
    const int ty = tid >> 4;
    const int pbase = blockIdx.x * FTP;

    if (tid < FTP) {
        sI[tid] = pi[pbase + tid];
        sJ[tid] = pj[pbase + tid];
    }
    __syncthreads();

    const int n0 = tx << 4;

    unsigned long long acc[4][8];
    #pragma unroll
    for (int s = 0; s < 4; s++)
        #pragma unroll
        for (int v = 0; v < 8; v++) acc[s][v] = 0ull;

    const int gp = tid >> 2;
    const int gk = (tid & 3) << 3;
    const int gi = sI[gp];
    const int gj = sJ[gp];
    const float* srcA = nodes + gi * Fdim;
    const float* srcB = nodes + gj * Fdim;
    const float* srcC = edges + ((size_t)gi * NA + gj) * FEdim;

    for (int kk = 0; kk < KX; kk += KC) {
        const float* src = (kk < Fdim)     ? (srcA + kk + gk)
                         : (kk < 2 * Fdim) ? (srcB + (kk - Fdim) + gk)
                                           : (srcC + (kk - 2 * Fdim) + gk);
        float4 v0 = *(const float4*)(src);
        float4 v1 = *(const float4*)(src + 4);
        *(float4*)(sX + gp * 36 + gk)     = v0;
        *(float4*)(sX + gp * 36 + gk + 4) = v1;

        {
            const float4* wsrc = (const float4*)(Wo1 + kk * HID);
            float4* wdst = (float4*)sW;
            #pragma unroll
            for (int t = 0; t < 8; t++) wdst[tid + t * NT] = wsrc[tid + t * NT];
        }
        __syncthreads();

        #pragma unroll
        for (int k = 0; k < KC; k++) {
            const ulonglong2* bp = (const ulonglong2*)(sW + k * HID + n0);
            ulonglong2 b0 = bp[0], b1 = bp[1], b2 = bp[2], b3 = bp[3];
            #pragma unroll
            for (int s = 0; s < 4; s++) {
                float a = sX[(ty + (s << 4)) * 36 + k];
                unsigned long long aa = pk2(a, a);
                fma2(acc[s][0], aa, b0.x); fma2(acc[s][1], aa, b0.y);
                fma2(acc[s][2], aa, b1.x); fma2(acc[s][3], aa, b1.y);
                fma2(acc[s][4], aa, b2.x); fma2(acc[s][5], aa, b2.y);
                fma2(acc[s][6], aa, b3.x); fma2(acc[s][7], aa, b3.y);
            }
        }
        __syncthreads();
    }

    #pragma unroll
    for (int v = 0; v < 8; v++) {
        float blo = bo1[n0 + 2 * v];
        float bhi = bo1[n0 + 2 * v + 1];
        #pragma unroll
        for (int s = 0; s < 4; s++) {
            float lo, hi;
            upk2(acc[s][v], lo, hi);
            lo = silu_f(lo + blo);
            hi = silu_f(hi + bhi);
            const int row = ty + (s << 4);
            sH[row * HID + n0 + 2 * v]     = lo;
            sH[row * HID + n0 + 2 * v + 1] = hi;
        }
    }
    __syncthreads();

    unsigned long long a2[4][7];
    #pragma unroll
    for (int s = 0; s < 4; s++)
        #pragma unroll
        for (int v = 0; v < 7; v++) a2[s][v] = 0ull;

    const int c0 = tx * 14;

    for (int kk = 0; kk < HID; kk += KC) {
        #pragma unroll
        for (int t = 0; t < 28; t++) {
            int e = tid + t * NT;
            int row = e / N2PAD;
            int col = e - row * N2PAD;
            sW[row * N2PAD + col] = (col < BB) ? Wo2[(kk + row) * BB + col] : 0.0f;
        }
        __syncthreads();

        #pragma unroll
        for (int k = 0; k < KC; k++) {
            const unsigned long long* bp = (const unsigned long long*)(sW + k * N2PAD + c0);
            unsigned long long b[7];
            #pragma unroll
            for (int v = 0; v < 7; v++) b[v] = bp[v];
            #pragma unroll
            for (int s = 0; s < 4; s++) {
                float a = sH[(ty + (s << 4)) * HID + kk + k];
                unsigned long long aa = pk2(a, a);
                #pragma unroll
                for (int v = 0; v < 7; v++) fma2(a2[s][v], aa, b[v]);
            }
        }
        __syncthreads();
    }

    if (tx < 14) {
        #pragma unroll
        for (int v = 0; v < 7; v++) {
            float blo = bo2[c0 + 2 * v];
            float bhi = bo2[c0 + 2 * v + 1];
            #pragma unroll
            for (int s = 0; s < 4; s++) {
                float lo, hi;
                upk2(a2[s][v], lo, hi);
                const int p = ty + (s << 4);
                sM[p * 200 + c0 + 2 * v]     = lo + blo;
                sM[p * 200 + c0 + 2 * v + 1] = hi + bhi;
            }
        }
    }
    __syncthreads();

    {
        const float* ovb = overlap + (size_t)pbase * BB;
        for (int e = tid; e < FTP * BB; e += NT) {
            int p = e / BB;
            sM[p * 200 + (e - p * BB)] += ovb[e];
        }
    }
    __syncthreads();

    for (int e = tid; e < FTP * BB; e += NT) {
        int p = e / BB;
        int idx = e - p * BB;
        int r = idx / Bb;
        int c = idx - r * Bb;
        out[(size_t)(sI[p] * Bb + r) * NBdim + sJ[p] * Bb + c] = sM[p * 200 + idx];
    }
    for (int e = tid; e < FTP * BB; e += NT) {
        int p = e / BB;
        int t = e - p * BB;
        int c = t / Bb;
        int r = t - c * Bb;
        out[(size_t)(sJ[p] * Bb + c) * NBdim + sI[p] * Bb + r] = sM[p * 200 + r * Bb + c];
    }
}

// ===========================================================================
// Diagonal kernel (tiny, FFMA everywhere)
// ===========================================================================
__global__ void __launch_bounds__(256)
diag_kernel(const float* __restrict__ nodes, const float* __restrict__ edges,
            const float* __restrict__ ablk,
            const float* __restrict__ W1, const float* __restrict__ b1,
            const float* __restrict__ W2, const float* __restrict__ b2,
            float* __restrict__ out)
{
    __shared__ float sx[HID];
    __shared__ float sh[HID];
    const int i = blockIdx.x;
    const int tid = threadIdx.x;

    sx[tid] = (tid < Fdim) ? nodes[i * Fdim + tid]
                           : edges[((size_t)i * NA + i) * FEdim + (tid - Fdim)];
    __syncthreads();

    float acc = b1[tid];
    #pragma unroll 8
    for (int k = 0; k < HID; k++)
        acc = fmaf(sx[k], W1[k * HID + tid], acc);
    sh[tid] = silu_f(acc);
    __syncthreads();

    if (tid < BB) {
        float a2 = b2[tid];
        #pragma unroll 8
        for (int k = 0; k < HID; k++)
            a2 = fmaf(sh[k], W2[k * BB + tid], a2);
        int r = tid / Bb;
        int c = tid - r * Bb;
        out[(size_t)(i * Bb + r) * NBdim + i * Bb + c] = a2 + ablk[i * BB + tid];
    }
}

// ===========================================================================
extern "C" void kernel_launch(void* const* d_in, const int* in_sizes, int n_in,
                              void* d_out, int out_size)
{
    const float* nodes = (const float*)d_in[0];
    const float* edges = (const float*)d_in[1];
    const float* ablk  = (const float*)d_in[2];
    const float* ovlp  = (const float*)d_in[3];
    const float* W1    = (const float*)d_in[4];
    const float* b1    = (const float*)d_in[5];
    const float* W2    = (const float*)d_in[6];
    const float* b2    = (const float*)d_in[7];
    const float* Wo1   = (const float*)d_in[8];
    const float* bo1   = (const float*)d_in[9];
    const float* Wo2   = (const float*)d_in[10];
    const float* bo2   = (const float*)d_in[11];
    const int*   pi    = (const int*)d_in[12];
    const int*   pj    = (const int*)d_in[13];
    float* out = (float*)d_out;

    const int P = in_sizes[12];   // 130816 = 1022*128 = 2044*64

    const int fb_smem = (FTP * 36 + KC * HID + FTP * HID + FTP * 200) * 4 + FTP * 2 * 4;
    cudaFuncSetAttribute(off_tc_kernel, cudaFuncAttributeMaxDynamicSharedMemorySize, SMEM_TOTAL);
    cudaFuncSetAttribute(off_kernel, cudaFuncAttributeMaxDynamicSharedMemorySize, fb_smem);

    // order chosen so ncu (-s 5 -c 1) captures off_tc_kernel on the 2nd replay
    prep_kernel<<<148, 256>>>(Wo1, Wo2);
    off_tc_kernel<<<P / TP, NT, SMEM_TOTAL>>>(nodes, edges, ovlp, bo1, bo2, pi, pj, out);
    diag_kernel<<<NA, 256>>>(nodes, edges, ablk, W1, b1, W2, b2, out);
    off_kernel<<<P / FTP, NT, fb_smem>>>(nodes, edges, ovlp, Wo1, bo1, Wo2, bo2, pi, pj, out);
}

// round 8
// speedup vs baseline: 7.4713x; 1.1727x over previous
#include <cuda_runtime.h>
#include <cuda_bf16.h>

#define NA    512
#define Fdim  128
#define FEdim 128
#define HID   256
#define Bb    14
#define BB    196
#define NBdim 7168
#define TP    128          // pairs per CTA
#define NT    256
#define N2PAD 224          // padded GEMM2 N (196 -> 224)

// -------- arch-feature detection: tcgen05 only exists on the 'a' target ----
#if defined(__CUDA_ARCH__) && \
    (defined(__CUDA_ARCH_FEAT_SM103_ALL) || \
     (defined(__CUDA_ARCH_SPECIFIC__) && (__CUDA_ARCH_SPECIFIC__ == 1030)) || \
     (defined(__CUDA_ARCH_FAMILY_SPECIFIC__) && (__CUDA_ARCH_FAMILY_SPECIFIC__ == 1030)))
#define HAS_TC 1
#else
#define HAS_TC 0
#endif

// ---------------- device scratch ----------------
__device__ __align__(16) __nv_bfloat16 g_W1T[HID * 384];     // [256][384]
__device__ __align__(16) __nv_bfloat16 g_W2T[N2PAD * HID];   // [224][256]

// ---------------- smem byte offsets (~104KB -> 2 CTAs/SM) ----------------
#define SM_X0    0         // X chunk buf0  [128][64]bf16 = 16384
#define SM_X1    16384
#define SM_W0    32768     // W1 chunk buf0 [256][64]bf16 = 32768
#define SM_W1    65536     // W1 chunk buf1
#define SM_H     0         // H [128][256]bf16, 4 chunk-blocks of 16384
#define SM_W2    65536     // W2 chunk [224][64]bf16 = 28672, single buf
#define SM_M     0         // sM [128][201] f32 = 102912
#define SM_BARS  102912    // +0 tmem ptr, +8 bar0, +16 bar1
#define SM_B1    102944    // bo1 256 f32
#define SM_B2    103968    // bo2 padded 224 f32
#define SM_IJ    104864    // 128 i + 128 j int
#define SMEM_TOTAL 105984

#define SW(o) ((o) ^ (((o) >> 3) & 0x70))

// idesc: dtype=F32, a=BF16, b=BF16, K-major, M=128
#define IDESC1 ((1u<<4)|(1u<<7)|(1u<<10)|((HID/8)<<17)|((128/16)<<24))    // N=256
#define IDESC2 ((1u<<4)|(1u<<7)|(1u<<10)|((N2PAD/8)<<17)|((128/16)<<24))  // N=224

// ---------------- generic helpers ----------------
__device__ __forceinline__ float silu_f(float x) { return x / (1.0f + __expf(-x)); }
__device__ __forceinline__ unsigned f2bf2(float lo, float hi) {
    __nv_bfloat162 h = __floats2bfloat162_rn(lo, hi);
    return *(unsigned*)&h;
}
__device__ __forceinline__ unsigned smem_u32(const void* p) {
    unsigned a;
    asm("{ .reg .u64 t; cvta.to.shared.u64 t, %1; cvt.u32.u64 %0, t; }" : "=r"(a) : "l"(p));
    return a;
}

#if HAS_TC
// ---------------- tcgen05 PTX helpers (only on the 'a' target) ----
__device__ __forceinline__ unsigned long long mk_desc(unsigned addr) {
    const unsigned long long base =
        (2ull << 61) | (1ull << 46) | (64ull << 32) | (1ull << 16);   // SW128, LBO=1, SBO=64
    return base | ((unsigned long long)(addr >> 4) & 0x3FFF);
}
__device__ __forceinline__ void mma_f16_ss(unsigned d, unsigned long long a,
                                           unsigned long long b, unsigned idesc, bool acc) {
    unsigned e = acc ? 1u : 0u;
    asm volatile(
        "{\n\t.reg .pred p;\n\t"
        "setp.ne.u32 p, %5, 0;\n\t"
        "tcgen05.mma.cta_group::1.kind::f16 [%0], %1, %2, %3, {%4,%4,%4,%4}, p;\n\t}"
        :: "r"(d), "l"(a), "l"(b), "r"(idesc), "r"(0u), "r"(e) : "memory");
}
__device__ __forceinline__ void tmem_alloc(unsigned smem_addr, unsigned ncols) {
    asm volatile("tcgen05.alloc.cta_group::1.sync.aligned.shared::cta.b32 [%0], %1;"
                 :: "r"(smem_addr), "r"(ncols) : "memory");
}
__device__ __forceinline__ void tmem_dealloc(unsigned tmem, unsigned ncols) {
    asm volatile("tcgen05.dealloc.cta_group::1.sync.aligned.b32 %0, %1;" :: "r"(tmem), "r"(ncols));
}
__device__ __forceinline__ void tmem_relinquish() {
    asm volatile("tcgen05.relinquish_alloc_permit.cta_group::1.sync.aligned;");
}
__device__ __forceinline__ void mbar_init(unsigned addr, unsigned cnt) {
    asm volatile("mbarrier.init.shared.b64 [%0], %1;" :: "r"(addr), "r"(cnt) : "memory");
}
__device__ __forceinline__ void mbar_wait(unsigned addr, unsigned parity) {
    asm volatile(
        "{\n\t.reg .pred P1;\n\t"
        "W%=:\n\t"
        "mbarrier.try_wait.parity.acquire.cta.shared::cta.b64 P1, [%0], %1, 0x989680;\n\t"
        "@P1 bra.uni D%=;\n\t"
        "bra.uni W%=;\n\t"
        "D%=:\n\t}"
        :: "r"(addr), "r"(parity) : "memory");
}
__device__ __forceinline__ void mma_commit(unsigned bar) {
    asm volatile("tcgen05.commit.cta_group::1.mbarrier::arrive::one.shared::cluster.b64 [%0];"
                 :: "r"(bar) : "memory");
}
__device__ __forceinline__ void fence_async_smem() {
    asm volatile("fence.proxy.async.shared::cta;" ::: "memory");
}
__device__ __forceinline__ void tc_fence_after() {
    asm volatile("tcgen05.fence::after_thread_sync;" ::: "memory");
}
__device__ __forceinline__ void tc_fence_before() {
    asm volatile("tcgen05.fence::before_thread_sync;" ::: "memory");
}
__device__ __forceinline__ void wait_ld() {
    asm volatile("tcgen05.wait::ld.sync.aligned;" ::: "memory");
}
__device__ __forceinline__ void ldtm32(unsigned* r, unsigned addr) {
    asm volatile(
        "tcgen05.ld.sync.aligned.32x32b.x32.b32 "
        "{%0,%1,%2,%3,%4,%5,%6,%7,%8,%9,%10,%11,%12,%13,%14,%15,"
        "%16,%17,%18,%19,%20,%21,%22,%23,%24,%25,%26,%27,%28,%29,%30,%31}, [%32];"
        : "=r"(r[0]),"=r"(r[1]),"=r"(r[2]),"=r"(r[3]),"=r"(r[4]),"=r"(r[5]),"=r"(r[6]),"=r"(r[7]),
          "=r"(r[8]),"=r"(r[9]),"=r"(r[10]),"=r"(r[11]),"=r"(r[12]),"=r"(r[13]),"=r"(r[14]),"=r"(r[15]),
          "=r"(r[16]),"=r"(r[17]),"=r"(r[18]),"=r"(r[19]),"=r"(r[20]),"=r"(r[21]),"=r"(r[22]),"=r"(r[23]),
          "=r"(r[24]),"=r"(r[25]),"=r"(r[26]),"=r"(r[27]),"=r"(r[28]),"=r"(r[29]),"=r"(r[30]),"=r"(r[31])
        : "r"(addr));
}
__device__ __forceinline__ void ldtm4(unsigned& a, unsigned& b, unsigned& c, unsigned& d, unsigned addr) {
    asm volatile("tcgen05.ld.sync.aligned.32x32b.x4.b32 {%0,%1,%2,%3}, [%4];"
                 : "=r"(a), "=r"(b), "=r"(c), "=r"(d) : "r"(addr));
}
#endif  // HAS_TC

// ===========================================================================
// prep: transpose + bf16-convert weights into device scratch
// ===========================================================================
__global__ void prep_kernel(const float* __restrict__ Wo1, const float* __restrict__ Wo2) {
    int stride = gridDim.x * blockDim.x;
    int t = blockIdx.x * blockDim.x + threadIdx.x;
    for (int e = t; e < HID * 384; e += stride) {
        int n = e / 384, k = e - n * 384;
        g_W1T[e] = __float2bfloat16(Wo1[k * HID + n]);
    }
    for (int e = t; e < N2PAD * HID; e += stride) {
        int n = e / HID, k = e - n * HID;
        g_W2T[e] = (n < BB) ? __float2bfloat16(Wo2[k * BB + n]) : __float2bfloat16(0.0f);
    }
}

// ===========================================================================
// Off-diagonal tcgen05 kernel: 128 pairs per CTA, 2 CTAs per SM
// ===========================================================================
__global__ void __launch_bounds__(NT, 2)
off_tc_kernel(const float* __restrict__ nodes, const float* __restrict__ edges,
              const float* __restrict__ overlap,
              const float* __restrict__ bo1, const float* __restrict__ bo2,
              const int* __restrict__ pi, const int* __restrict__ pj,
              float* __restrict__ out)
{
#if HAS_TC
    extern __shared__ char smem[];
    const unsigned sb = smem_u32(smem);
    const int tid = threadIdx.x;
    const int pbase = blockIdx.x * TP;

    int*   sI  = (int*)(smem + SM_IJ);
    int*   sJ  = sI + TP;
    float* sB1 = (float*)(smem + SM_B1);
    float* sB2 = (float*)(smem + SM_B2);

    if (tid < TP) { sI[tid] = pi[pbase + tid]; sJ[tid] = pj[pbase + tid]; }
    sB1[tid] = bo1[tid];
    if (tid < N2PAD) sB2[tid] = (tid < BB) ? bo2[tid] : 0.0f;

    if (tid == 0) {
        mbar_init(sb + SM_BARS + 8, 1);
        mbar_init(sb + SM_BARS + 16, 1);
    }
    if (tid < 32) {
        tmem_alloc(sb + SM_BARS, 256);   // D1 0..255; D2 reuses 0..223
        tmem_relinquish();
    }
    __syncthreads();

    unsigned tmem;
    asm volatile("ld.shared.b32 %0, [%1];" : "=r"(tmem) : "r"(sb + SM_BARS));
    const unsigned bar0 = sb + SM_BARS + 8;
    const unsigned bar1 = sb + SM_BARS + 16;
    int cnt0 = 0, cnt1 = 0;

    // gather mapping: 8 lanes per pair-row segment (coalesced 32B/lane)
    const int gseg = tid & 7;
    const int grow0 = tid >> 3;

    // ---------------- GEMM1: D1[128,256] = X[128,384] @ Wo1, K chunks of 64
    #pragma unroll 1
    for (int c = 0; c < 6; c++) {
        const int b = c & 1;
        if (c >= 2) {
            if (b == 0) { mbar_wait(bar0, cnt0 & 1); cnt0++; }
            else        { mbar_wait(bar1, cnt1 & 1); cnt1++; }
        }
        // X chunk gather+convert -> swizzled smem [128][64]bf16 (coalesced)
        {
            char* xdst = smem + (b ? SM_X1 : SM_X0);
            #pragma unroll
            for (int it = 0; it < 4; it++) {
                const int p = grow0 + it * 32;
                const int xi = sI[p], xj = sJ[p];
                const float* s;
                if (c < 2)      s = nodes + (size_t)xi * Fdim + c * 64;
                else if (c < 4) s = nodes + (size_t)xj * Fdim + (c - 2) * 64;
                else            s = edges + ((size_t)xi * NA + xj) * FEdim + (c - 4) * 64;
                s += gseg * 8;
                float4 v0 = *(const float4*)(s);
                float4 v1 = *(const float4*)(s + 4);
                uint4 w;
                w.x = f2bf2(v0.x, v0.y); w.y = f2bf2(v0.z, v0.w);
                w.z = f2bf2(v1.x, v1.y); w.w = f2bf2(v1.z, v1.w);
                *(uint4*)(xdst + SW(p * 128 + gseg * 16)) = w;
            }
        }
        // W1 chunk [256][64]bf16 -> swizzled smem (index-linear, coalesced)
        {
            char* wdst = smem + (b ? SM_W1 : SM_W0);
            #pragma unroll
            for (int t = 0; t < 8; t++) {
                int e = tid + t * NT;         // 0..2047
                int row = e >> 3, g = e & 7;
                uint4 v = *(const uint4*)(g_W1T + (size_t)row * 384 + c * 64 + g * 8);
                *(uint4*)(wdst + SW(row * 128 + g * 16)) = v;
            }
        }
        fence_async_smem();
        __syncthreads();
        if (tid == 0) {
            unsigned long long ad = mk_desc(sb + (b ? SM_X1 : SM_X0));
            unsigned long long bd = mk_desc(sb + (b ? SM_W1 : SM_W0));
            #pragma unroll
            for (int ks = 0; ks < 4; ks++)
                mma_f16_ss(tmem, ad + ks * 2, bd + ks * 2, IDESC1, (c > 0) || (ks > 0));
            mma_commit(b ? bar1 : bar0);
        }
    }
    mbar_wait(bar0, cnt0 & 1); cnt0++;
    mbar_wait(bar1, cnt1 & 1); cnt1++;
    tc_fence_after();

    // ---------------- epilogue1 (8-warp split): D1 -> silu -> bf16 H in smem
    // warps 0-3: TMEM cols 0..127 (cb 0-3) then W2 chunk0; warps 4-7: cols 128..255
    {
        const int row = tid & 127;
        const int cb0 = (tid < 128) ? 0 : 4;
        unsigned regs[32];
        #pragma unroll 1
        for (int cb = cb0; cb < cb0 + 4; cb++) {
            ldtm32(regs, tmem + cb * 32);
            wait_ld();
            #pragma unroll
            for (int t = 0; t < 8; t++) {
                int n0 = cb * 32 + t * 4;
                float a0 = silu_f(__uint_as_float(regs[t * 4 + 0]) + sB1[n0 + 0]);
                float a1 = silu_f(__uint_as_float(regs[t * 4 + 1]) + sB1[n0 + 1]);
                float a2 = silu_f(__uint_as_float(regs[t * 4 + 2]) + sB1[n0 + 2]);
                float a3 = silu_f(__uint_as_float(regs[t * 4 + 3]) + sB1[n0 + 3]);
                uint2 w; w.x = f2bf2(a0, a1); w.y = f2bf2(a2, a3);
                unsigned off = row * 128 + ((n0 & 63) << 1);
                *(uint2*)(smem + SM_H + ((n0 >> 6) << 14) + SW(off)) = w;
            }
        }
        tc_fence_before();
        if (tid < 128) {
            // W2 chunk 0 -> smem (1792 uint4 = 14 * 128)
            #pragma unroll
            for (int t = 0; t < 14; t++) {
                int e = tid + t * 128;
                int r2 = e >> 3, g = e & 7;
                uint4 v = *(const uint4*)(g_W2T + (size_t)r2 * HID + g * 8);
                *(uint4*)(smem + SM_W2 + SW(r2 * 128 + g * 16)) = v;
            }
        }
    }

    // ---------------- GEMM2: D2[128,224] = H[128,256] @ Wo2pad (D2 reuses D1 cols)
    // single smem buffer + register prefetch of next chunk during MMA
    #pragma unroll 1
    for (int q = 0; q < 4; q++) {
        fence_async_smem();
        __syncthreads();
        if (tid == 0) {
            if (q == 0) tc_fence_after();
            unsigned long long ad = mk_desc(sb + SM_H + q * 16384);
            unsigned long long bd = mk_desc(sb + SM_W2);
            #pragma unroll
            for (int ks = 0; ks < 4; ks++)
                mma_f16_ss(tmem, ad + ks * 2, bd + ks * 2, IDESC2, (q > 0) || (ks > 0));
            mma_commit(bar0);
        }
        if (q < 3) {
            // prefetch next W2 chunk into regs while MMA q runs
            uint4 wreg[7];
            #pragma unroll
            for (int t = 0; t < 7; t++) {
                int e = tid + t * NT;              // < 1792 exactly
                int r2 = e >> 3, g = e & 7;
                wreg[t] = *(const uint4*)(g_W2T + (size_t)r2 * HID + (q + 1) * 64 + g * 8);
            }
            mbar_wait(bar0, cnt0 & 1); cnt0++;     // MMA q done reading smem W2
            #pragma unroll
            for (int t = 0; t < 7; t++) {
                int e = tid + t * NT;
                int r2 = e >> 3, g = e & 7;
                *(uint4*)(smem + SM_W2 + SW(r2 * 128 + g * 16)) = wreg[t];
            }
        }
    }
    mbar_wait(bar0, cnt0 & 1); cnt0++;
    tc_fence_after();

    // ---------------- epilogue2 (8-warp split): D2 + bias -> sM [128][201] f32
    {
        const int row = tid & 127;
        float* rowM = (float*)(smem + SM_M) + row * 201;
        unsigned regs[32];
        const int cb0 = (tid < 128) ? 0 : 3;
        #pragma unroll 1
        for (int cb = cb0; cb < cb0 + 3; cb++) {
            ldtm32(regs, tmem + cb * 32);
            wait_ld();
            #pragma unroll
            for (int c = 0; c < 32; c++)
                rowM[cb * 32 + c] = __uint_as_float(regs[c]) + sB2[cb * 32 + c];
        }
        if (tid >= 128) {
            unsigned r0, r1, r2, r3;
            ldtm4(r0, r1, r2, r3, tmem + 192);
            wait_ld();
            rowM[192] = __uint_as_float(r0) + sB2[192];
            rowM[193] = __uint_as_float(r1) + sB2[193];
            rowM[194] = __uint_as_float(r2) + sB2[194];
            rowM[195] = __uint_as_float(r3) + sB2[195];
        }
        tc_fence_before();
    }
    __syncthreads();

    // ---------------- add overlap (float4-coalesced) ----------------
    {
        const float4* ovb4 = (const float4*)(overlap + (size_t)pbase * BB);  // 16B aligned
        float* sM = (float*)(smem + SM_M);
        #pragma unroll 1
        for (int t = 0; t < 25; t++) {
            int e = tid + t * NT;              // 6272 float4 total (49 per pair)
            if (e < TP * BB / 4) {
                float4 v = ovb4[e];
                int p = e / 49;
                int idx = (e - p * 49) * 4;
                float* dst = sM + p * 201 + idx;
                dst[0] += v.x; dst[1] += v.y; dst[2] += v.z; dst[3] += v.w;
            }
        }
    }
    __syncthreads();

    // ---------------- scatter: float2 stores, exact counts ----------------
    {
        const float* sM = (const float*)(smem + SM_M);
        // (i,j) blocks: 12544 float2 = 49 * NT; run = 7 float2 per (p,r)
        #pragma unroll 1
        for (int t = 0; t < 49; t++) {
            int e = tid + t * NT;
            int p = e / 98;
            int q2 = e - p * 98;
            int r = q2 / 7;
            int c2 = q2 - r * 7;
            const float* src = sM + p * 201 + r * 14 + c2 * 2;
            float2 v = make_float2(src[0], src[1]);
            *(float2*)(out + (size_t)(sI[p] * Bb + r) * NBdim + sJ[p] * Bb + c2 * 2) = v;
        }
        // (j,i) transposed blocks: runs along r
        #pragma unroll 1
        for (int t = 0; t < 49; t++) {
            int e = tid + t * NT;
            int p = e / 98;
            int q2 = e - p * 98;
            int c = q2 / 7;
            int k = q2 - c * 7;
            const float* src = sM + p * 201 + (2 * k) * 14 + c;
            float2 v = make_float2(src[0], src[14]);
            *(float2*)(out + (size_t)(sJ[p] * Bb + c) * NBdim + sI[p] * Bb + 2 * k) = v;
        }
    }
    __syncthreads();
    if (tid < 32) tmem_dealloc(tmem, 256);
#endif  // HAS_TC (stub on non-'a' virtual pass; sm_103a cubin is what runs)
}

// ===========================================================================
// Diagonal kernel (tiny)
// ===========================================================================
__global__ void __launch_bounds__(256)
diag_kernel(const float* __restrict__ nodes, const float* __restrict__ edges,
            const float* __restrict__ ablk,
            const float* __restrict__ W1, const float* __restrict__ b1,
            const float* __restrict__ W2, const float* __restrict__ b2,
            float* __restrict__ out)
{
    __shared__ float sx[HID];
    __shared__ float sh[HID];
    const int i = blockIdx.x;
    const int tid = threadIdx.x;

    sx[tid] = (tid < Fdim) ? nodes[i * Fdim + tid]
                           : edges[((size_t)i * NA + i) * FEdim + (tid - Fdim)];
    __syncthreads();

    float acc = b1[tid];
    #pragma unroll 8
    for (int k = 0; k < HID; k++)
        acc = fmaf(sx[k], W1[k * HID + tid], acc);
    sh[tid] = silu_f(acc);
    __syncthreads();

    if (tid < BB) {
        float a2 = b2[tid];
        #pragma unroll 8
        for (int k = 0; k < HID; k++)
            a2 = fmaf(sh[k], W2[k * BB + tid], a2);
        int r = tid / Bb;
        int c = tid - r * Bb;
        out[(size_t)(i * Bb + r) * NBdim + i * Bb + c] = a2 + ablk[i * BB + tid];
    }
}

// ===========================================================================
extern "C" void kernel_launch(void* const* d_in, const int* in_sizes, int n_in,
                              void* d_out, int out_size)
{
    const float* nodes = (const float*)d_in[0];
    const float* edges = (const float*)d_in[1];
    const float* ablk  = (const float*)d_in[2];
    const float* ovlp  = (const float*)d_in[3];
    const float* W1    = (const float*)d_in[4];
    const float* b1    = (const float*)d_in[5];
    const float* W2    = (const float*)d_in[6];
    const float* b2    = (const float*)d_in[7];
    const float* Wo1   = (const float*)d_in[8];
    const float* bo1   = (const float*)d_in[9];
    const float* Wo2   = (const float*)d_in[10];
    const float* bo2   = (const float*)d_in[11];
    const int*   pi    = (const int*)d_in[12];
    const int*   pj    = (const int*)d_in[13];
    float* out = (float*)d_out;

    const int P = in_sizes[12];   // 130816 = 1022 * 128

    cudaFuncSetAttribute(off_tc_kernel, cudaFuncAttributeMaxDynamicSharedMemorySize, SMEM_TOTAL);

    // 3 launches/call, off_tc last: ncu -s 5 -c 1 lands on off_tc (launch #6)
    prep_kernel<<<148, 256>>>(Wo1, Wo2);
    diag_kernel<<<NA, 256>>>(nodes, edges, ablk, W1, b1, W2, b2, out);
    off_tc_kernel<<<P / TP, NT, SMEM_TOTAL>>>(nodes, edges, ovlp, bo1, bo2, pi, pj, out);
}